// round 7
// baseline (speedup 1.0000x reference)
#include <cuda_runtime.h>
#include <cstdint>

#define Bn    16
#define Sn    1024
#define Dn    512
#define KCn   12
#define Kn    10
#define NT    128
#define SCN   32          // s-chunks per batch
#define CSL   32          // s per chunk
#define NDH   2           // d halves
#define NGRP  4           // level-1 groups (8 chunks each)

typedef unsigned long long ull;
#define ONE2 0x3f8000003f800000ull

__device__ ull   g_part[Bn * NDH * SCN][Kn][NT];   // 10.5 MB chunk partials
__device__ ull   g_l1[Bn * NDH * NGRP][Kn][NT];    // 1.3 MB level-1 partials
__device__ float g_asum[Bn * SCN][Kn];
__device__ float g_asum1[Bn][NGRP][Kn];
__device__ int   g_cnt1[Bn * NDH * NGRP];
__device__ int   g_cnt2[Bn];

__device__ __forceinline__ void fma2(ull& acc, ull a, ull f) {
    asm("fma.rn.f32x2 %0, %1, %2, %0;" : "+l"(acc) : "l"(a), "l"(f));
}

__global__ __launch_bounds__(NT, 8)
void vlad_tlp(const float* __restrict__ feat, const float* __restrict__ score,
              const float* __restrict__ cluster, float* __restrict__ out)
{
    __shared__ __align__(16) ull Ash[CSL][Kn];   // duplicated {a,a} pairs, 2.5 KB
    __shared__ float asumT[Kn];
    __shared__ float invS[Kn];
    __shared__ float sqw[Kn][4];
    __shared__ int   fL1, fL2;

    const int tid = threadIdx.x;
    const int b  = blockIdx.x >> 6;
    const int dh = (blockIdx.x >> 5) & 1;
    const int sc = blockIdx.x & 31;

    // ---- softmax: warp 0, one s-row each (rows sc*32 .. sc*32+31) ----
    if (tid < CSL) {
        const float* sp = score + ((size_t)(b * Sn) + sc * CSL + tid) * KCn;
        float4 v0 = *(const float4*)sp;
        float4 v1 = *(const float4*)(sp + 4);
        float4 v2 = *(const float4*)(sp + 8);
        float v[KCn] = {v0.x, v0.y, v0.z, v0.w, v1.x, v1.y, v1.z, v1.w,
                        v2.x, v2.y, v2.z, v2.w};
        float sum = 0.f;
        #pragma unroll
        for (int k = 0; k < KCn; k++) { v[k] = __expf(v[k]); sum += v[k]; }
        float inv = 1.f / sum;
        #pragma unroll
        for (int k = 0; k < Kn; k++) {
            float a = v[k] * inv;
            unsigned int u = __float_as_uint(a);
            Ash[tid][k] = ((ull)u << 32) | (ull)u;
            if (dh == 0) {               // chunk asum (dh==0 CTA only)
                float s = a;
                #pragma unroll
                for (int o = 16; o > 0; o >>= 1) s += __shfl_xor_sync(0xffffffffu, s, o);
                if (tid == 0) g_asum[b * SCN + sc][k] = s;
            }
        }
    }
    __syncthreads();

    // ---- main loop: thread owns d = dh*256 + tid*2, walks 32 s-rows ----
    ull acc[Kn];
    #pragma unroll
    for (int k = 0; k < Kn; k++) acc[k] = 0ull;

    const ull* fp = (const ull*)feat
                  + ((size_t)(b * Sn) + sc * CSL) * (Dn / 2) + dh * 128 + tid;
    #pragma unroll
    for (int i = 0; i < CSL; i += 4) {
        ull f0 = fp[(size_t)(i + 0) * 256];
        ull f1 = fp[(size_t)(i + 1) * 256];
        ull f2 = fp[(size_t)(i + 2) * 256];
        ull f3 = fp[(size_t)(i + 3) * 256];
        #pragma unroll
        for (int j = 0; j < 4; j++) {
            const ull f = (j == 0) ? f0 : (j == 1) ? f1 : (j == 2) ? f2 : f3;
            const ulonglong2* ar = (const ulonglong2*)Ash[i + j];
            ulonglong2 a01 = ar[0], a23 = ar[1], a45 = ar[2], a67 = ar[3], a89 = ar[4];
            fma2(acc[0], a01.x, f); fma2(acc[1], a01.y, f);
            fma2(acc[2], a23.x, f); fma2(acc[3], a23.y, f);
            fma2(acc[4], a45.x, f); fma2(acc[5], a45.y, f);
            fma2(acc[6], a67.x, f); fma2(acc[7], a67.y, f);
            fma2(acc[8], a89.x, f); fma2(acc[9], a89.y, f);
        }
    }

    // ---- write chunk partial (thread owns its slot, no reduction) ----
    const int chunk = (b * NDH + dh) * SCN + sc;
    #pragma unroll
    for (int k = 0; k < Kn; k++) g_part[chunk][k][tid] = acc[k];

    // ---- level-1: last of 8 chunks in my group folds them ----
    const int g = sc >> 3;
    const int ci = (b * NDH + dh) * NGRP + g;
    __threadfence();
    __syncthreads();
    if (tid == 0) fL1 = (atomicAdd(&g_cnt1[ci], 1) == 7);
    __syncthreads();
    if (!fL1) return;
    __threadfence();

    const int c0 = (b * NDH + dh) * SCN + g * 8;
    #pragma unroll
    for (int k = 0; k < Kn; k++) {
        ull a = g_part[c0][k][tid];
        #pragma unroll
        for (int c = 1; c < 8; c++) fma2(a, g_part[c0 + c][k][tid], ONE2);
        g_l1[ci][k][tid] = a;
    }
    if (dh == 0 && tid < Kn) {
        float s = 0.f;
        #pragma unroll
        for (int c = 0; c < 8; c++) s += g_asum[b * SCN + g * 8 + c][tid];
        g_asum1[b][g][tid] = s;
    }

    // ---- level-2: last of 8 level-1 mergers for this batch finalizes ----
    __threadfence();
    __syncthreads();
    if (tid == 0) {
        g_cnt1[ci] = 0;                       // reset for next replay
        fL2 = (atomicAdd(&g_cnt2[b], 1) == 7);
    }
    __syncthreads();
    if (!fL2) return;
    __threadfence();

    if (tid < Kn) {
        float s = 0.f;
        #pragma unroll
        for (int gg = 0; gg < NGRP; gg++) s += g_asum1[b][gg][tid];
        asumT[tid] = s;
    }
    __syncthreads();

    ull* ob = (ull*)out + (size_t)b * 2560;   // batch slice, 2560 d-pairs
    float sqp[Kn];
    #pragma unroll
    for (int k = 0; k < Kn; k++) sqp[k] = 0.f;

    #pragma unroll
    for (int w = 0; w < 20; w++) {
        const int idx = tid + w * NT;         // 0..2559
        const int k = idx >> 8, dp = idx & 255;
        const int dhh = dp >> 7, lp = dp & 127;
        const int li = (b * NDH + dhh) * NGRP;
        ull a = g_l1[li][k][lp];
        fma2(a, g_l1[li + 1][k][lp], ONE2);
        fma2(a, g_l1[li + 2][k][lp], ONE2);
        fma2(a, g_l1[li + 3][k][lp], ONE2);
        const float as = asumT[k];
        float2 cl = *(const float2*)(cluster + k * Dn + dp * 2);
        float rx = __uint_as_float((unsigned int)a)         - as * cl.x;
        float ry = __uint_as_float((unsigned int)(a >> 32)) - as * cl.y;
        unsigned int ux = __float_as_uint(rx), uy = __float_as_uint(ry);
        ob[idx] = ((ull)uy << 32) | (ull)ux;
        sqp[k] += rx * rx + ry * ry;
    }
    #pragma unroll
    for (int k = 0; k < Kn; k++) {
        float s = sqp[k];
        #pragma unroll
        for (int o = 16; o > 0; o >>= 1) s += __shfl_xor_sync(0xffffffffu, s, o);
        if ((tid & 31) == 0) sqw[k][tid >> 5] = s;
    }
    __syncthreads();
    if (tid < Kn)
        invS[tid] = rsqrtf(fmaxf(sqw[tid][0] + sqw[tid][1] + sqw[tid][2] + sqw[tid][3],
                                 1e-12f));
    __syncthreads();
    #pragma unroll
    for (int w = 0; w < 20; w++) {
        const int idx = tid + w * NT;
        const float iv = invS[idx >> 8];
        ull a = ob[idx];
        float rx = __uint_as_float((unsigned int)a) * iv;
        float ry = __uint_as_float((unsigned int)(a >> 32)) * iv;
        unsigned int ux = __float_as_uint(rx), uy = __float_as_uint(ry);
        ob[idx] = ((ull)uy << 32) | (ull)ux;
    }
    if (tid == 0) g_cnt2[b] = 0;              // reset for next replay
}

extern "C" void kernel_launch(void* const* d_in, const int* in_sizes, int n_in,
                              void* d_out, int out_size) {
    const float* feat    = (const float*)d_in[0];  // (16,16,64,512) f32
    const float* score   = (const float*)d_in[1];  // (16,16,64,12)  f32
    const float* cluster = (const float*)d_in[2];  // (12,512)       f32
    float* out = (float*)d_out;                    // (16,5120)      f32

    vlad_tlp<<<Bn * NDH * SCN, NT>>>(feat, score, cluster, out);
}

// round 8
// speedup vs baseline: 1.4751x; 1.4751x over previous
#include <cuda_runtime.h>
#include <cstdint>

#define Bn    16
#define Sn    1024
#define Dn    512
#define KCn   12
#define Kn    10
#define NSC   16          // s-chunks per batch
#define CSL   64          // s per chunk (contiguous 128 KB)
#define NT    256

typedef unsigned long long ull;
#define ONE2 0x3f8000003f800000ull

__device__ ull   g_part[Bn * NSC][Kn][NT];   // 5.24 MB chunk partials (L2-resident scratch)
__device__ float g_asum[Bn * NSC][Kn];
__device__ int   g_cnt[Bn];

__device__ __forceinline__ void fma2(ull& acc, ull a, ull f) {
    asm("fma.rn.f32x2 %0, %1, %2, %0;" : "+l"(acc) : "l"(a), "l"(f));
}

__global__ __launch_bounds__(NT, 2)
void vlad_stream(const float* __restrict__ feat, const float* __restrict__ score,
                 const float* __restrict__ cluster, float* __restrict__ out)
{
    __shared__ __align__(16) ull Ash[CSL][Kn];   // duplicated {a,a} pairs, 5 KB
    __shared__ float wsum[2][Kn];
    __shared__ float asumT[Kn];
    __shared__ float invS[Kn];
    __shared__ float sqw[Kn][8];
    __shared__ int   isLast;

    const int tid = threadIdx.x;
    const int b  = blockIdx.x >> 4;
    const int sc = blockIdx.x & 15;
    const int chunk = b * NSC + sc;

    // ---- softmax: threads 0..63, one s-row each ----
    if (tid < CSL) {
        const float* sp = score + ((size_t)(b * Sn) + sc * CSL + tid) * KCn;
        float4 v0 = *(const float4*)sp;
        float4 v1 = *(const float4*)(sp + 4);
        float4 v2 = *(const float4*)(sp + 8);
        float v[KCn] = {v0.x, v0.y, v0.z, v0.w, v1.x, v1.y, v1.z, v1.w,
                        v2.x, v2.y, v2.z, v2.w};
        float sum = 0.f;
        #pragma unroll
        for (int k = 0; k < KCn; k++) { v[k] = __expf(v[k]); sum += v[k]; }
        float inv = 1.f / sum;
        #pragma unroll
        for (int k = 0; k < Kn; k++) {
            float a = v[k] * inv;
            unsigned int u = __float_as_uint(a);
            Ash[tid][k] = ((ull)u << 32) | (ull)u;
            float s = a;
            #pragma unroll
            for (int o = 16; o > 0; o >>= 1) s += __shfl_xor_sync(0xffffffffu, s, o);
            if ((tid & 31) == 0) wsum[tid >> 5][k] = s;
        }
    }
    __syncthreads();
    if (tid < Kn) g_asum[chunk][tid] = wsum[0][tid] + wsum[1][tid];

    // ---- main loop: thread owns d-pair tid; CTA streams 64 contiguous rows ----
    ull acc[Kn];
    #pragma unroll
    for (int k = 0; k < Kn; k++) acc[k] = 0ull;

    const ull* fp = (const ull*)feat + ((size_t)(b * Sn) + sc * CSL) * (Dn / 2) + tid;

    for (int i = 0; i < CSL; i += 8) {
        ull f[8];
        #pragma unroll
        for (int j = 0; j < 8; j++) f[j] = fp[(size_t)(i + j) * (Dn / 2)];
        #pragma unroll
        for (int j = 0; j < 8; j++) {
            const ulonglong2* ar = (const ulonglong2*)Ash[i + j];
            ulonglong2 a01 = ar[0], a23 = ar[1], a45 = ar[2], a67 = ar[3], a89 = ar[4];
            fma2(acc[0], a01.x, f[j]); fma2(acc[1], a01.y, f[j]);
            fma2(acc[2], a23.x, f[j]); fma2(acc[3], a23.y, f[j]);
            fma2(acc[4], a45.x, f[j]); fma2(acc[5], a45.y, f[j]);
            fma2(acc[6], a67.x, f[j]); fma2(acc[7], a67.y, f[j]);
            fma2(acc[8], a89.x, f[j]); fma2(acc[9], a89.y, f[j]);
        }
    }

    // ---- write chunk partial (thread owns its slot; no reduction needed) ----
    #pragma unroll
    for (int k = 0; k < Kn; k++) g_part[chunk][k][tid] = acc[k];

    // ---- last CTA of this batch merges the 16 chunk partials ----
    __threadfence();
    __syncthreads();
    if (tid == 0) isLast = (atomicAdd(&g_cnt[b], 1) == NSC - 1);
    __syncthreads();
    if (!isLast) return;
    __threadfence();

    if (tid < Kn) {
        float s = 0.f;
        #pragma unroll
        for (int c = 0; c < NSC; c++) s += g_asum[b * NSC + c][tid];
        asumT[tid] = s;
    }
    __syncthreads();

    ull* ob = (ull*)out + (size_t)b * (Kn * Dn / 2);   // 2560 d-pairs
    float sq[Kn];

    #pragma unroll
    for (int k = 0; k < Kn; k++) {                     // w-th pass is center k
        ull a = g_part[b * NSC][k][tid];
        #pragma unroll
        for (int c = 1; c < NSC; c++) fma2(a, g_part[b * NSC + c][k][tid], ONE2);
        const float as = asumT[k];
        float2 cl = *(const float2*)(cluster + k * Dn + tid * 2);
        float rx = __uint_as_float((unsigned int)a)         - as * cl.x;
        float ry = __uint_as_float((unsigned int)(a >> 32)) - as * cl.y;
        unsigned int ux = __float_as_uint(rx), uy = __float_as_uint(ry);
        ob[k * (Dn / 2) + tid] = ((ull)uy << 32) | (ull)ux;
        sq[k] = rx * rx + ry * ry;
    }
    #pragma unroll
    for (int k = 0; k < Kn; k++) {
        float s = sq[k];
        #pragma unroll
        for (int o = 16; o > 0; o >>= 1) s += __shfl_xor_sync(0xffffffffu, s, o);
        if ((tid & 31) == 0) sqw[k][tid >> 5] = s;
    }
    __syncthreads();
    if (tid < Kn) {
        float s = 0.f;
        #pragma unroll
        for (int w = 0; w < 8; w++) s += sqw[tid][w];
        invS[tid] = rsqrtf(fmaxf(s, 1e-12f));
    }
    __syncthreads();
    #pragma unroll
    for (int k = 0; k < Kn; k++) {
        const float iv = invS[k];
        ull a = ob[k * (Dn / 2) + tid];
        float rx = __uint_as_float((unsigned int)a) * iv;
        float ry = __uint_as_float((unsigned int)(a >> 32)) * iv;
        unsigned int ux = __float_as_uint(rx), uy = __float_as_uint(ry);
        ob[k * (Dn / 2) + tid] = ((ull)uy << 32) | (ull)ux;
    }
    if (tid == 0) g_cnt[b] = 0;   // reset for next graph replay
}

extern "C" void kernel_launch(void* const* d_in, const int* in_sizes, int n_in,
                              void* d_out, int out_size) {
    const float* feat    = (const float*)d_in[0];  // (16,16,64,512) f32
    const float* score   = (const float*)d_in[1];  // (16,16,64,12)  f32
    const float* cluster = (const float*)d_in[2];  // (12,512)       f32
    float* out = (float*)d_out;                    // (16,5120)      f32

    vlad_stream<<<Bn * NSC, NT>>>(feat, score, cluster, out);
}

// round 9
// speedup vs baseline: 1.7936x; 1.2159x over previous
#include <cuda_runtime.h>
#include <cstdint>

#define Bn    16
#define Sn    1024
#define Dn    512
#define KCn   12
#define Kn    10
#define NSC   8           // s-chunks per batch
#define CSL   128         // s per chunk (contiguous 256 KB per CTA)
#define NT    256

typedef unsigned long long ull;
#define ONE2 0x3f8000003f800000ull

__device__ ull   g_part[Bn * NSC][Kn][NT];   // 2.6 MB chunk partials (L2-hot scratch)
__device__ float g_asum[Bn * NSC][Kn];
__device__ int   g_cnt[Bn];

__device__ __forceinline__ void fma2(ull& acc, ull a, ull f) {
    asm("fma.rn.f32x2 %0, %1, %2, %0;" : "+l"(acc) : "l"(a), "l"(f));
}

__global__ __launch_bounds__(NT, 1)
void vlad_k1f(const float* __restrict__ feat, const float* __restrict__ score,
              const float* __restrict__ cluster, float* __restrict__ out)
{
    __shared__ __align__(16) ull Ash[CSL][Kn];   // duplicated {a,a} pairs, 10 KB
    __shared__ float wsum[4][Kn];
    __shared__ float asumT[Kn];
    __shared__ float invS[Kn];
    __shared__ float sqw[Kn][8];
    __shared__ int   isLast;

    const int tid = threadIdx.x;
    const int b  = blockIdx.x >> 3;
    const int sc = blockIdx.x & 7;
    const int chunk = b * NSC + sc;

    // ---- softmax: threads 0..127, one s-row each ----
    if (tid < CSL) {
        const float* sp = score + ((size_t)(b * Sn) + sc * CSL + tid) * KCn;
        float4 v0 = *(const float4*)sp;
        float4 v1 = *(const float4*)(sp + 4);
        float4 v2 = *(const float4*)(sp + 8);
        float v[KCn] = {v0.x, v0.y, v0.z, v0.w, v1.x, v1.y, v1.z, v1.w,
                        v2.x, v2.y, v2.z, v2.w};
        float sum = 0.f;
        #pragma unroll
        for (int k = 0; k < KCn; k++) { v[k] = __expf(v[k]); sum += v[k]; }
        float inv = 1.f / sum;
        #pragma unroll
        for (int k = 0; k < Kn; k++) {
            float a = v[k] * inv;
            unsigned int u = __float_as_uint(a);
            Ash[tid][k] = ((ull)u << 32) | (ull)u;
            float s = a;
            #pragma unroll
            for (int o = 16; o > 0; o >>= 1) s += __shfl_xor_sync(0xffffffffu, s, o);
            if ((tid & 31) == 0) wsum[tid >> 5][k] = s;
        }
    }
    __syncthreads();
    if (tid < Kn)
        g_asum[chunk][tid] = wsum[0][tid] + wsum[1][tid] + wsum[2][tid] + wsum[3][tid];

    // ---- main loop (R1-K1 geometry): thread owns d-pair tid, 128 s-rows ----
    ull acc[Kn];
    #pragma unroll
    for (int k = 0; k < Kn; k++) acc[k] = 0ull;

    const ull* fp = (const ull*)feat + ((size_t)(b * Sn) + sc * CSL) * (Dn / 2) + tid;

    #pragma unroll 8
    for (int s = 0; s < CSL; s++) {
        ull f = fp[(size_t)s * (Dn / 2)];
        const ulonglong2* ar = (const ulonglong2*)Ash[s];
        ulonglong2 a01 = ar[0], a23 = ar[1], a45 = ar[2], a67 = ar[3], a89 = ar[4];
        fma2(acc[0], a01.x, f); fma2(acc[1], a01.y, f);
        fma2(acc[2], a23.x, f); fma2(acc[3], a23.y, f);
        fma2(acc[4], a45.x, f); fma2(acc[5], a45.y, f);
        fma2(acc[6], a67.x, f); fma2(acc[7], a67.y, f);
        fma2(acc[8], a89.x, f); fma2(acc[9], a89.y, f);
    }

    // ---- write chunk partial (thread owns its slot) ----
    #pragma unroll
    for (int k = 0; k < Kn; k++) g_part[chunk][k][tid] = acc[k];

    // ---- last CTA of this batch merges the 8 chunk partials ----
    __threadfence();
    __syncthreads();
    if (tid == 0) isLast = (atomicAdd(&g_cnt[b], 1) == NSC - 1);
    __syncthreads();
    if (!isLast) return;
    __threadfence();

    if (tid < Kn) {
        float s = 0.f;
        #pragma unroll
        for (int c = 0; c < NSC; c++) s += g_asum[b * NSC + c][tid];
        asumT[tid] = s;
    }
    __syncthreads();

    // residuals held in registers: 10 k x 1 ull per thread (d-pair tid)
    float2 r[Kn];
    #pragma unroll
    for (int k = 0; k < Kn; k++) {
        ull a = g_part[b * NSC][k][tid];
        #pragma unroll
        for (int c = 1; c < NSC; c++) fma2(a, g_part[b * NSC + c][k][tid], ONE2);
        const float as = asumT[k];
        float2 cl = *(const float2*)(cluster + k * Dn + tid * 2);
        r[k].x = __uint_as_float((unsigned int)a)         - as * cl.x;
        r[k].y = __uint_as_float((unsigned int)(a >> 32)) - as * cl.y;
        float s = r[k].x * r[k].x + r[k].y * r[k].y;
        #pragma unroll
        for (int o = 16; o > 0; o >>= 1) s += __shfl_xor_sync(0xffffffffu, s, o);
        if ((tid & 31) == 0) sqw[k][tid >> 5] = s;
    }
    __syncthreads();
    if (tid < Kn) {
        float s = 0.f;
        #pragma unroll
        for (int w = 0; w < 8; w++) s += sqw[tid][w];
        invS[tid] = rsqrtf(fmaxf(s, 1e-12f));
    }
    __syncthreads();

    ull* ob = (ull*)out + (size_t)b * (Kn * Dn / 2);
    #pragma unroll
    for (int k = 0; k < Kn; k++) {
        const float iv = invS[k];
        unsigned int ux = __float_as_uint(r[k].x * iv);
        unsigned int uy = __float_as_uint(r[k].y * iv);
        ob[k * (Dn / 2) + tid] = ((ull)uy << 32) | (ull)ux;
    }
    if (tid == 0) g_cnt[b] = 0;   // reset for next graph replay
}

extern "C" void kernel_launch(void* const* d_in, const int* in_sizes, int n_in,
                              void* d_out, int out_size) {
    const float* feat    = (const float*)d_in[0];  // (16,16,64,512) f32
    const float* score   = (const float*)d_in[1];  // (16,16,64,12)  f32
    const float* cluster = (const float*)d_in[2];  // (12,512)       f32
    float* out = (float*)d_out;                    // (16,5120)      f32

    vlad_k1f<<<Bn * NSC, NT>>>(feat, score, cluster, out);
}